// round 15
// baseline (speedup 1.0000x reference)
#include <cuda_runtime.h>
#include <cuda_fp16.h>
#include <cstdint>

#define NW     16384
#define MAXLEN 16
#define VOCAB  128
#define EMB    64
#define HID    256
#define G4     1024

// ---------------- static device state (no allocation) ----------------
// P table fp16, gate-interleaved: [dir][v][j 0..255][gate i,f,g,o]
__device__ __align__(16) __half d_P4[(size_t)2 * VOCAB * HID * 4];
__device__ float d_C[(size_t)2 * NW * HID];           // c: [dir][slot][j]
__device__ float d_Hfin[(size_t)2 * NW * HID];        // final h: [dir][slot][j]
// H fp16: [buf][dir][slot][k]
__device__ __align__(16) __half d_Hh[(size_t)2 * 2 * NW * HID];
// W u64-interleaved: [dir][jb4(4)][chunk(4)][256 rows (g*64+jl)][pitch 20 u64]
__device__ __align__(16) __half d_Wimg[(size_t)2 * 4 * 4 * 256 * 80];
__device__ int   d_cursor[MAXLEN + 2];
__device__ int   d_offset[MAXLEN + 2];
__device__ int   d_nactive[MAXLEN];
__device__ int   d_word_of_slot[NW];
__device__ unsigned char d_slot_len[NW];
__device__ unsigned char d_chars[2][MAXLEN][NW];

// ---------------- helpers ----------------
__device__ __forceinline__ float sigm(float x) {
    return __fdividef(1.f, 1.f + __expf(-x));
}
__device__ __forceinline__ float ftanh(float x) {
    float e = __expf(-2.f * x);
    return __fdividef(1.f - e, 1.f + e);
}
__device__ __forceinline__ void mma_f16(float c[4], const uint32_t a[4],
                                        uint32_t b0, uint32_t b1) {
    asm volatile(
        "mma.sync.aligned.m16n8k16.row.col.f32.f16.f16.f32 "
        "{%0,%1,%2,%3}, {%4,%5,%6,%7}, {%8,%9}, {%0,%1,%2,%3};"
        : "+f"(c[0]), "+f"(c[1]), "+f"(c[2]), "+f"(c[3])
        : "r"(a[0]), "r"(a[1]), "r"(a[2]), "r"(a[3]), "r"(b0), "r"(b1));
}
__device__ __forceinline__ void ldsm4(uint32_t r[4], uint32_t addr) {
    asm volatile("ldmatrix.sync.aligned.m8n8.x4.shared.b16 {%0,%1,%2,%3}, [%4];"
        : "=r"(r[0]), "=r"(r[1]), "=r"(r[2]), "=r"(r[3]) : "r"(addr));
}
__device__ __forceinline__ void lds64(uint32_t& b0, uint32_t& b1, uint32_t addr) {
    asm volatile("ld.shared.v2.b32 {%0,%1}, [%2];" : "=r"(b0), "=r"(b1) : "r"(addr));
}
__device__ __forceinline__ uint32_t smem_u32(const void* p) {
    uint32_t a;
    asm("{ .reg .u64 t; cvta.to.shared.u64 t, %1; cvt.u32.u64 %0, t; }" : "=r"(a) : "l"(p));
    return a;
}
__device__ __forceinline__ void cp16(uint32_t dst, const void* src) {
    asm volatile("cp.async.cg.shared.global [%0], [%1], 16;" :: "r"(dst), "l"(src) : "memory");
}
__device__ __forceinline__ void cp_commit() {
    asm volatile("cp.async.commit_group;" ::: "memory");
}
template <int N>
__device__ __forceinline__ void cp_wait() {
    asm volatile("cp.async.wait_group %0;" :: "n"(N) : "memory");
}
__device__ __forceinline__ void gdc_wait() {
    asm volatile("griddepcontrol.wait;" ::: "memory");
}
__device__ __forceinline__ void gdc_launch() {
    asm volatile("griddepcontrol.launch_dependents;" ::: "memory");
}

// ---------------- setup: hist + scan + cursor (one block) ----------------
__global__ void k_setup(const int* __restrict__ lengths) {
    __shared__ int sh[MAXLEN + 2];
    int tid = threadIdx.x;                      // 1024
    if (tid <= MAXLEN + 1) sh[tid] = 0;
    __syncthreads();
    for (int w = tid; w < NW; w += 1024) atomicAdd(&sh[lengths[w]], 1);
    __syncthreads();
    if (tid == 0) {
        int off = 0;
        for (int L = MAXLEN; L >= 1; L--) { d_offset[L] = off; off += sh[L]; }
        for (int t = 0; t < MAXLEN; t++) {
            int n = 0;
            for (int L = t + 1; L <= MAXLEN; L++) n += sh[L];
            d_nactive[t] = n;
        }
    }
    if (tid <= MAXLEN + 1) d_cursor[tid] = 0;
}

// ---------------- prep: W u64-interleaved image + P4 table ----------------
__global__ void k_prep(const float* __restrict__ emb,
                       const float* __restrict__ WihF, const float* __restrict__ bihF,
                       const float* __restrict__ bhhF,
                       const float* __restrict__ WihB, const float* __restrict__ bihB,
                       const float* __restrict__ bhhB,
                       const float* __restrict__ WhhF, const float* __restrict__ WhhB) {
    if (blockIdx.x < 2048) {
        int i = blockIdx.x * 256 + threadIdx.x;    // 2*1024*256
        int dir = i >> 18;
        int e = i & 0x3FFFF;
        int row = e >> 8, k = e & 255;
        int g = row >> 8, j = row & 255;
        int jb4 = j >> 6, jl = j & 63;
        int r256 = g * 64 + jl;
        int ch = k >> 6, kl = k & 63;
        int q = (kl >> 4) * 4 + ((kl & 7) >> 1);
        int pos = (kl & 1) + (((kl & 15) >= 8) ? 2 : 0);
        float x = (dir ? WhhB : WhhF)[(size_t)row * 256 + k];
        d_Wimg[(((size_t)((dir * 4 + jb4) * 4 + ch) * 256 + r256) * 20 + q) * 4 + pos]
            = __float2half_rn(x);
    } else {
        int bid = blockIdx.x - 2048;
        int v = bid & 127, d = bid >> 7;
        const float* Wih = d ? WihB : WihF;
        const float* bih = d ? bihB : bihF;
        const float* bhh = d ? bhhB : bhhF;
        __shared__ float esm[EMB];
        if (threadIdx.x < EMB) esm[threadIdx.x] = emb[v * EMB + threadIdx.x];
        __syncthreads();
#pragma unroll
        for (int q = 0; q < 4; q++) {
            int j = threadIdx.x + q * 256;         // 0..1023 gate-major row
            const float* wr = &Wih[j * EMB];
            float s = 0.f;
#pragma unroll
            for (int k = 0; k < EMB; k += 4) {
                float4 wv = *reinterpret_cast<const float4*>(&wr[k]);
                s += esm[k] * wv.x + esm[k + 1] * wv.y + esm[k + 2] * wv.z + esm[k + 3] * wv.w;
            }
            int g = j >> 8, jc = j & 255;
            d_P4[(((size_t)(d * VOCAB + v) * HID + jc) << 2) + g]
                = __float2half_rn(s + bih[j] + bhh[j]);
        }
    }
}

// ---------------- scatter + step 0 (h0 = 0 -> gates = P[char]) ----------------
__global__ void __launch_bounds__(512)
k_scatter0(const int* __restrict__ lengths, const int* __restrict__ char_ids) {
    int tid = threadIdx.x;
    int wloc = tid >> 3, sub = tid & 7;
    int w = blockIdx.x * 64 + wloc;
    __shared__ int spos[64];
    int len = lengths[w];
    if (sub == 0) {
        int pos = d_offset[len] + atomicAdd(&d_cursor[len], 1);
        spos[wloc] = pos;
        d_word_of_slot[pos] = w;
        d_slot_len[pos] = (unsigned char)len;
    }
    __syncthreads();
    int pos = spos[wloc];
#pragma unroll
    for (int tt = sub * 2; tt < sub * 2 + 2; tt++) {
        d_chars[0][tt][pos] = (unsigned char)char_ids[w * MAXLEN + tt];
        int r = len - 1 - tt; if (r < 0) r = 0;
        d_chars[1][tt][pos] = (unsigned char)char_ids[w * MAXLEN + r];
    }
    int dir = sub >> 2;
    int j0 = (sub & 3) * 64;
    int v = char_ids[w * MAXLEN + (dir ? (len - 1) : 0)];
    const __half* Pv = d_P4 + (((size_t)(dir * VOCAB + v) * HID) << 2);
    bool last = (len == 1);
    float* crow = &d_C[((size_t)dir * NW + pos) * HID];
    float* frow = &d_Hfin[((size_t)dir * NW + pos) * HID];
    __half* hrow = d_Hh + ((size_t)(2 + dir) * NW + pos) * HID;   // buf 1
#pragma unroll 2
    for (int q = 0; q < 64; q += 2) {
        float hv[2];
        uint4 pk = *reinterpret_cast<const uint4*>(&Pv[(j0 + q) << 2]);
        const __half2* ph = reinterpret_cast<const __half2*>(&pk);
#pragma unroll
        for (int u = 0; u < 2; u++) {
            int j = j0 + q + u;
            float pi = __half2float(ph[2 * u].x);
            float pg = __half2float(ph[2 * u + 1].x);
            float po = __half2float(ph[2 * u + 1].y);
            float c1 = sigm(pi) * ftanh(pg);
            float h1 = sigm(po) * ftanh(c1);
            crow[j] = c1;
            if (last) frow[j] = h1;
            hv[u] = h1;
        }
        __half2 h2v; h2v.x = __float2half_rn(hv[0]); h2v.y = __float2half_rn(hv[1]);
        *reinterpret_cast<__half2*>(&hrow[j0 + q]) = h2v;
    }
}

// ---------------- fused recurrent step (t >= 1) ----------------
// Block: 64 slots x 64 j x 4 gates, 8 warps. Warp tile 32 slots x 64 n:
// ws = warp&1, wj = warp>>1 (4 x 16 j). Per kk4: 2 LDSM + 8 LDS.64 + 16 MMA.
#define TILE_A  9216                           // 64 * 144
#define TILE_W  40960                          // 256 * 160
#define SM_W0   (2 * TILE_A)                   // 18432
#define SM_TOT  (SM_W0 + 2 * TILE_W)           // 100352

__global__ void __launch_bounds__(256, 2) k_step(int t) {
    gdc_wait();                                // PDL: prior step's H fully visible
    const int nact = d_nactive[t];
    const int slot0 = blockIdx.x * 64;
    if (slot0 >= nact) { gdc_launch(); return; }
    const int jb = blockIdx.y, j0 = jb * 64;
    const int dir = blockIdx.z;
    const int rb = t & 1, wb = rb ^ 1;

    extern __shared__ __align__(16) char smem[];
    const uint32_t sb = smem_u32(smem);
    const char* __restrict__ Hr = (const char*)(d_Hh + (size_t)(rb * 2 + dir) * NW * HID);
    const char* wimg = (const char*)d_Wimg + (size_t)(dir * 4 + jb) * 4 * TILE_W;

    const int tid = threadIdx.x;
    const int warp = tid >> 5, lane = tid & 31;
    const int ws = warp & 1, wj = warp >> 1;
    const int g4 = lane >> 2, t4 = lane & 3;

    const uint32_t arow_off = (uint32_t)(ws * 32 + (lane & 15)) * 144 + ((lane & 16) ? 16 : 0);

    float acc[4][2][2][4];                     // [gate][nf][mh][frag]
#pragma unroll
    for (int g = 0; g < 4; g++)
#pragma unroll
        for (int nf = 0; nf < 2; nf++)
#pragma unroll
            for (int mh = 0; mh < 2; mh++)
#pragma unroll
                for (int r = 0; r < 4; r++) acc[g][nf][mh][r] = 0.f;

    // branch-free staging: 2 A segs + 10 W segs per thread
    const int sA0 = tid >> 3, koA = (tid & 7) * 16;
    auto issue_chunk = [&](int c, int buf) {
        uint32_t asB = sb + buf * TILE_A;
        uint32_t wsB = sb + SM_W0 + buf * TILE_W;
        const char* wsrc = wimg + c * TILE_W;
        cp16(asB + sA0 * 144 + koA,
             Hr + (size_t)(slot0 + sA0) * 512 + c * 128 + koA);
        cp16(asB + (sA0 + 32) * 144 + koA,
             Hr + (size_t)(slot0 + sA0 + 32) * 512 + c * 128 + koA);
#pragma unroll
        for (int i = 0; i < 10; i++) {
            int r = (tid + i * 256) * 16;
            cp16(wsB + r, wsrc + r);
        }
    };

    issue_chunk(0, 0); cp_commit();
    issue_chunk(1, 1); cp_commit();

#pragma unroll 1
    for (int c = 0; c < 4; c++) {
        if (c < 3) cp_wait<1>(); else cp_wait<0>();
        __syncthreads();
        const int buf = c & 1;
        const uint32_t aB = sb + buf * TILE_A + arow_off;
        const uint32_t wB = sb + SM_W0 + buf * TILE_W;
#pragma unroll
        for (int kk4 = 0; kk4 < 4; kk4++) {
            uint32_t a0[4], a1[4];
            ldsm4(a0, aB + kk4 * 32);
            ldsm4(a1, aB + 2304 + kk4 * 32);      // mh=1: +16 rows * 144 B
            const int qb = kk4 * 4 + t4;
#pragma unroll
            for (int g = 0; g < 4; g++) {
#pragma unroll
                for (int nf = 0; nf < 2; nf++) {
                    int row = g * 64 + wj * 16 + nf * 8 + g4;
                    uint32_t b0, b1;
                    lds64(b0, b1, wB + (uint32_t)(row * 20 + qb) * 8);
                    mma_f16(acc[g][nf][0], a0, b0, b1);
                    mma_f16(acc[g][nf][1], a1, b0, b1);
                }
            }
        }
        __syncthreads();
        if (c + 2 < 4) { issue_chunk(c + 2, buf); cp_commit(); }
    }

    // ---- epilogue: LSTM cell, all 4 gates thread-local (16 cells/thread) ----
    __half* HW = d_Hh + (size_t)(wb * 2 + dir) * NW * HID;
    const int jbase = j0 + wj * 16;
#pragma unroll
    for (int mh = 0; mh < 2; mh++) {
#pragma unroll
        for (int rh = 0; rh < 2; rh++) {
            int s = slot0 + ws * 32 + mh * 16 + rh * 8 + g4;
            if (s >= nact) continue;
            int v = d_chars[dir][t][s];
            bool last = (t == (int)d_slot_len[s] - 1);
            float* crow = &d_C[((size_t)dir * NW + s) * HID];
            float* frow = &d_Hfin[((size_t)dir * NW + s) * HID];
            __half* hrow = &HW[(size_t)s * HID];
            const __half* Pv = &d_P4[(((size_t)(dir * VOCAB + v) * HID) << 2)];
#pragma unroll
            for (int nf = 0; nf < 2; nf++) {
                int jp = jbase + nf * 8 + 2 * t4;
                uint4 pk = *reinterpret_cast<const uint4*>(&Pv[jp << 2]);
                const __half2* ph = reinterpret_cast<const __half2*>(&pk);
                float2 cc = *reinterpret_cast<const float2*>(&crow[jp]);
                float cin[2] = {cc.x, cc.y};
                float hv[2], cv[2];
#pragma unroll
                for (int cp = 0; cp < 2; cp++) {
                    float ai = acc[0][nf][mh][rh * 2 + cp] + __half2float(ph[2 * cp].x);
                    float af = acc[1][nf][mh][rh * 2 + cp] + __half2float(ph[2 * cp].y);
                    float ag = acc[2][nf][mh][rh * 2 + cp] + __half2float(ph[2 * cp + 1].x);
                    float ao = acc[3][nf][mh][rh * 2 + cp] + __half2float(ph[2 * cp + 1].y);
                    float c2 = sigm(af) * cin[cp] + sigm(ai) * ftanh(ag);
                    float h2 = sigm(ao) * ftanh(c2);
                    cv[cp] = c2;
                    hv[cp] = h2;
                }
                *reinterpret_cast<float2*>(&crow[jp]) = make_float2(cv[0], cv[1]);
                if (last)
                    *reinterpret_cast<float2*>(&frow[jp]) = make_float2(hv[0], hv[1]);
                __half2 h2v;
                h2v.x = __float2half_rn(hv[0]);
                h2v.y = __float2half_rn(hv[1]);
                *reinterpret_cast<__half2*>(&hrow[jp]) = h2v;
            }
        }
    }
    gdc_launch();
}

// ---------------- gather output ----------------
__global__ void k_out(float* __restrict__ out) {
    gdc_wait();
    int s = blockIdx.x;
    int tid = threadIdx.x;
    int w = d_word_of_slot[s];
    int dir = tid >> 8, j = tid & 255;
    out[(size_t)w * 512 + tid] = d_Hfin[((size_t)dir * NW + s) * HID + j];
}

// ---------------- launch ----------------
extern "C" void kernel_launch(void* const* d_in, const int* in_sizes, int n_in,
                              void* d_out, int out_size) {
    const int*   char_ids = (const int*)d_in[0];
    const int*   lengths  = (const int*)d_in[1];
    const float* emb      = (const float*)d_in[2];
    const float* WihF = (const float*)d_in[3];
    const float* WhhF = (const float*)d_in[4];
    const float* bihF = (const float*)d_in[5];
    const float* bhhF = (const float*)d_in[6];
    const float* WihB = (const float*)d_in[7];
    const float* WhhB = (const float*)d_in[8];
    const float* bihB = (const float*)d_in[9];
    const float* bhhB = (const float*)d_in[10];
    float* out = (float*)d_out;

    static bool s_init = false;
    if (!s_init) {
        cudaFuncSetAttribute(k_step, cudaFuncAttributeMaxDynamicSharedMemorySize, SM_TOT);
        s_init = true;
    }

    k_setup<<<1, 1024>>>(lengths);
    k_prep<<<2048 + 256, 256>>>(emb, WihF, bihF, bhhF, WihB, bihB, bhhB, WhhF, WhhB);
    k_scatter0<<<NW / 64, 512>>>(lengths, char_ids);

    cudaLaunchAttribute pdl[1];
    pdl[0].id = cudaLaunchAttributeProgrammaticStreamSerialization;
    pdl[0].val.programmaticStreamSerializationAllowed = 1;
    for (int t = 1; t < MAXLEN; t++) {
        cudaLaunchConfig_t cfg = {};
        cfg.gridDim = dim3(NW / 64, 4, 2);
        cfg.blockDim = dim3(256, 1, 1);
        cfg.dynamicSmemBytes = SM_TOT;
        cfg.stream = 0;
        cfg.attrs = pdl;
        cfg.numAttrs = 1;
        cudaLaunchKernelEx(&cfg, k_step, t);
    }
    {
        cudaLaunchConfig_t cfg = {};
        cfg.gridDim = dim3(NW, 1, 1);
        cfg.blockDim = dim3(512, 1, 1);
        cfg.dynamicSmemBytes = 0;
        cfg.stream = 0;
        cfg.attrs = pdl;
        cfg.numAttrs = 1;
        cudaLaunchKernelEx(&cfg, k_out, out);
    }
}

// round 16
// speedup vs baseline: 1.0009x; 1.0009x over previous
#include <cuda_runtime.h>
#include <cuda_fp16.h>
#include <cstdint>

#define NW     16384
#define MAXLEN 16
#define VOCAB  128
#define EMB    64
#define HID    256
#define G4     1024

// ---------------- static device state (no allocation) ----------------
// P table fp16, gate-interleaved: [dir][v][j 0..255][gate i,f,g,o]
__device__ __align__(16) __half d_P4[(size_t)2 * VOCAB * HID * 4];
__device__ float d_C[(size_t)2 * NW * HID];           // c: [dir][slot][j]
__device__ float d_Hfin[(size_t)2 * NW * HID];        // final h: [dir][slot][j]
// H fp16: [buf][dir][slot][k]
__device__ __align__(16) __half d_Hh[(size_t)2 * 2 * NW * HID];
// W u64-interleaved: [dir][jb4(4)][chunk(4)][256 rows (g*64+jl)][pitch 20 u64]
__device__ __align__(16) __half d_Wimg[(size_t)2 * 4 * 4 * 256 * 80];
__device__ int   d_cursor[MAXLEN + 2];
__device__ int   d_offset[MAXLEN + 2];
__device__ int   d_nactive[MAXLEN];
__device__ int   d_word_of_slot[NW];
__device__ unsigned char d_slot_len[NW];
__device__ unsigned char d_chars[2][MAXLEN][NW];

// ---------------- helpers ----------------
__device__ __forceinline__ float sigm(float x) {
    return __fdividef(1.f, 1.f + __expf(-x));
}
__device__ __forceinline__ float ftanh(float x) {
    float e = __expf(-2.f * x);
    return __fdividef(1.f - e, 1.f + e);
}
__device__ __forceinline__ void mma_f16(float c[4], const uint32_t a[4],
                                        uint32_t b0, uint32_t b1) {
    asm volatile(
        "mma.sync.aligned.m16n8k16.row.col.f32.f16.f16.f32 "
        "{%0,%1,%2,%3}, {%4,%5,%6,%7}, {%8,%9}, {%0,%1,%2,%3};"
        : "+f"(c[0]), "+f"(c[1]), "+f"(c[2]), "+f"(c[3])
        : "r"(a[0]), "r"(a[1]), "r"(a[2]), "r"(a[3]), "r"(b0), "r"(b1));
}
__device__ __forceinline__ void ldsm4(uint32_t r[4], uint32_t addr) {
    asm volatile("ldmatrix.sync.aligned.m8n8.x4.shared.b16 {%0,%1,%2,%3}, [%4];"
        : "=r"(r[0]), "=r"(r[1]), "=r"(r[2]), "=r"(r[3]) : "r"(addr));
}
__device__ __forceinline__ void lds64(uint32_t& b0, uint32_t& b1, uint32_t addr) {
    asm volatile("ld.shared.v2.b32 {%0,%1}, [%2];" : "=r"(b0), "=r"(b1) : "r"(addr));
}
__device__ __forceinline__ uint32_t smem_u32(const void* p) {
    uint32_t a;
    asm("{ .reg .u64 t; cvta.to.shared.u64 t, %1; cvt.u32.u64 %0, t; }" : "=r"(a) : "l"(p));
    return a;
}
__device__ __forceinline__ void cp16(uint32_t dst, const void* src) {
    asm volatile("cp.async.cg.shared.global [%0], [%1], 16;" :: "r"(dst), "l"(src) : "memory");
}
__device__ __forceinline__ void cp_commit() {
    asm volatile("cp.async.commit_group;" ::: "memory");
}
template <int N>
__device__ __forceinline__ void cp_wait() {
    asm volatile("cp.async.wait_group %0;" :: "n"(N) : "memory");
}
__device__ __forceinline__ void gdc_wait() {
    asm volatile("griddepcontrol.wait;" ::: "memory");
}
__device__ __forceinline__ void gdc_launch() {
    asm volatile("griddepcontrol.launch_dependents;" ::: "memory");
}

// ---------------- setup: hist + scan + cursor (one block) ----------------
__global__ void k_setup(const int* __restrict__ lengths) {
    __shared__ int sh[MAXLEN + 2];
    int tid = threadIdx.x;                      // 1024
    if (tid <= MAXLEN + 1) sh[tid] = 0;
    __syncthreads();
    for (int w = tid; w < NW; w += 1024) atomicAdd(&sh[lengths[w]], 1);
    __syncthreads();
    if (tid == 0) {
        int off = 0;
        for (int L = MAXLEN; L >= 1; L--) { d_offset[L] = off; off += sh[L]; }
        for (int t = 0; t < MAXLEN; t++) {
            int n = 0;
            for (int L = t + 1; L <= MAXLEN; L++) n += sh[L];
            d_nactive[t] = n;
        }
    }
    if (tid <= MAXLEN + 1) d_cursor[tid] = 0;
}

// ---------------- prep: W u64-interleaved image + P4 table ----------------
__global__ void k_prep(const float* __restrict__ emb,
                       const float* __restrict__ WihF, const float* __restrict__ bihF,
                       const float* __restrict__ bhhF,
                       const float* __restrict__ WihB, const float* __restrict__ bihB,
                       const float* __restrict__ bhhB,
                       const float* __restrict__ WhhF, const float* __restrict__ WhhB) {
    if (blockIdx.x < 2048) {
        int i = blockIdx.x * 256 + threadIdx.x;    // 2*1024*256
        int dir = i >> 18;
        int e = i & 0x3FFFF;
        int row = e >> 8, k = e & 255;
        int g = row >> 8, j = row & 255;
        int jb4 = j >> 6, jl = j & 63;
        int r256 = g * 64 + jl;
        int ch = k >> 6, kl = k & 63;
        int q = (kl >> 4) * 4 + ((kl & 7) >> 1);
        int pos = (kl & 1) + (((kl & 15) >= 8) ? 2 : 0);
        float x = (dir ? WhhB : WhhF)[(size_t)row * 256 + k];
        d_Wimg[(((size_t)((dir * 4 + jb4) * 4 + ch) * 256 + r256) * 20 + q) * 4 + pos]
            = __float2half_rn(x);
    } else {
        int bid = blockIdx.x - 2048;
        int v = bid & 127, d = bid >> 7;
        const float* Wih = d ? WihB : WihF;
        const float* bih = d ? bihB : bihF;
        const float* bhh = d ? bhhB : bhhF;
        __shared__ float esm[EMB];
        if (threadIdx.x < EMB) esm[threadIdx.x] = emb[v * EMB + threadIdx.x];
        __syncthreads();
#pragma unroll
        for (int q = 0; q < 4; q++) {
            int j = threadIdx.x + q * 256;         // 0..1023 gate-major row
            const float* wr = &Wih[j * EMB];
            float s = 0.f;
#pragma unroll
            for (int k = 0; k < EMB; k += 4) {
                float4 wv = *reinterpret_cast<const float4*>(&wr[k]);
                s += esm[k] * wv.x + esm[k + 1] * wv.y + esm[k + 2] * wv.z + esm[k + 3] * wv.w;
            }
            int g = j >> 8, jc = j & 255;
            d_P4[(((size_t)(d * VOCAB + v) * HID + jc) << 2) + g]
                = __float2half_rn(s + bih[j] + bhh[j]);
        }
    }
}

// ---------------- scatter + step 0 (h0 = 0 -> gates = P[char]) ----------------
__global__ void __launch_bounds__(512)
k_scatter0(const int* __restrict__ lengths, const int* __restrict__ char_ids) {
    int tid = threadIdx.x;
    int wloc = tid >> 3, sub = tid & 7;
    int w = blockIdx.x * 64 + wloc;
    __shared__ int spos[64];
    int len = lengths[w];
    if (sub == 0) {
        int pos = d_offset[len] + atomicAdd(&d_cursor[len], 1);
        spos[wloc] = pos;
        d_word_of_slot[pos] = w;
        d_slot_len[pos] = (unsigned char)len;
    }
    __syncthreads();
    int pos = spos[wloc];
#pragma unroll
    for (int tt = sub * 2; tt < sub * 2 + 2; tt++) {
        d_chars[0][tt][pos] = (unsigned char)char_ids[w * MAXLEN + tt];
        int r = len - 1 - tt; if (r < 0) r = 0;
        d_chars[1][tt][pos] = (unsigned char)char_ids[w * MAXLEN + r];
    }
    int dir = sub >> 2;
    int j0 = (sub & 3) * 64;
    int v = char_ids[w * MAXLEN + (dir ? (len - 1) : 0)];
    const __half* Pv = d_P4 + (((size_t)(dir * VOCAB + v) * HID) << 2);
    bool last = (len == 1);
    float* crow = &d_C[((size_t)dir * NW + pos) * HID];
    float* frow = &d_Hfin[((size_t)dir * NW + pos) * HID];
    __half* hrow = d_Hh + ((size_t)(2 + dir) * NW + pos) * HID;   // buf 1
#pragma unroll 2
    for (int q = 0; q < 64; q += 2) {
        float hv[2];
        uint4 pk = *reinterpret_cast<const uint4*>(&Pv[(j0 + q) << 2]);
        const __half2* ph = reinterpret_cast<const __half2*>(&pk);
#pragma unroll
        for (int u = 0; u < 2; u++) {
            int j = j0 + q + u;
            float pi = __half2float(ph[2 * u].x);
            float pg = __half2float(ph[2 * u + 1].x);
            float po = __half2float(ph[2 * u + 1].y);
            float c1 = sigm(pi) * ftanh(pg);
            float h1 = sigm(po) * ftanh(c1);
            crow[j] = c1;
            if (last) frow[j] = h1;
            hv[u] = h1;
        }
        __half2 h2v; h2v.x = __float2half_rn(hv[0]); h2v.y = __float2half_rn(hv[1]);
        *reinterpret_cast<__half2*>(&hrow[j0 + q]) = h2v;
    }
}

// ---------------- fused recurrent step (t >= 1) ----------------
// Block: 64 slots x 64 j x 4 gates, 8 warps. Warp tile 32 slots x 64 n:
// ws = warp&1, wj = warp>>1 (4 x 16 j). Per kk4: 2 LDSM + 8 LDS.64 + 16 MMA.
#define TILE_A  9216                           // 64 * 144
#define TILE_W  40960                          // 256 * 160
#define SM_W0   (2 * TILE_A)                   // 18432
#define SM_TOT  (SM_W0 + 2 * TILE_W)           // 100352

__global__ void __launch_bounds__(256, 2) k_step(int t) {
    gdc_wait();                                // PDL: prior step's H fully visible
    const int nact = d_nactive[t];
    const int slot0 = blockIdx.x * 64;
    if (slot0 >= nact) { gdc_launch(); return; }
    const int jb = blockIdx.y, j0 = jb * 64;
    const int dir = blockIdx.z;
    const int rb = t & 1, wb = rb ^ 1;

    extern __shared__ __align__(16) char smem[];
    const uint32_t sb = smem_u32(smem);
    const char* __restrict__ Hr = (const char*)(d_Hh + (size_t)(rb * 2 + dir) * NW * HID);
    const char* wimg = (const char*)d_Wimg + (size_t)(dir * 4 + jb) * 4 * TILE_W;

    const int tid = threadIdx.x;
    const int warp = tid >> 5, lane = tid & 31;
    const int ws = warp & 1, wj = warp >> 1;
    const int g4 = lane >> 2, t4 = lane & 3;

    const uint32_t arow_off = (uint32_t)(ws * 32 + (lane & 15)) * 144 + ((lane & 16) ? 16 : 0);

    float acc[4][2][2][4];                     // [gate][nf][mh][frag]
#pragma unroll
    for (int g = 0; g < 4; g++)
#pragma unroll
        for (int nf = 0; nf < 2; nf++)
#pragma unroll
            for (int mh = 0; mh < 2; mh++)
#pragma unroll
                for (int r = 0; r < 4; r++) acc[g][nf][mh][r] = 0.f;

    // branch-free staging: 2 A segs + 10 W segs per thread
    const int sA0 = tid >> 3, koA = (tid & 7) * 16;
    auto issue_chunk = [&](int c, int buf) {
        uint32_t asB = sb + buf * TILE_A;
        uint32_t wsB = sb + SM_W0 + buf * TILE_W;
        const char* wsrc = wimg + c * TILE_W;
        cp16(asB + sA0 * 144 + koA,
             Hr + (size_t)(slot0 + sA0) * 512 + c * 128 + koA);
        cp16(asB + (sA0 + 32) * 144 + koA,
             Hr + (size_t)(slot0 + sA0 + 32) * 512 + c * 128 + koA);
#pragma unroll
        for (int i = 0; i < 10; i++) {
            int r = (tid + i * 256) * 16;
            cp16(wsB + r, wsrc + r);
        }
    };

    issue_chunk(0, 0); cp_commit();
    issue_chunk(1, 1); cp_commit();

#pragma unroll 1
    for (int c = 0; c < 4; c++) {
        if (c < 3) cp_wait<1>(); else cp_wait<0>();
        __syncthreads();
        const int buf = c & 1;
        const uint32_t aB = sb + buf * TILE_A + arow_off;
        const uint32_t wB = sb + SM_W0 + buf * TILE_W;
#pragma unroll
        for (int kk4 = 0; kk4 < 4; kk4++) {
            uint32_t a0[4], a1[4];
            ldsm4(a0, aB + kk4 * 32);
            ldsm4(a1, aB + 2304 + kk4 * 32);      // mh=1: +16 rows * 144 B
            const int qb = kk4 * 4 + t4;
#pragma unroll
            for (int g = 0; g < 4; g++) {
#pragma unroll
                for (int nf = 0; nf < 2; nf++) {
                    int row = g * 64 + wj * 16 + nf * 8 + g4;
                    uint32_t b0, b1;
                    lds64(b0, b1, wB + (uint32_t)(row * 20 + qb) * 8);
                    mma_f16(acc[g][nf][0], a0, b0, b1);
                    mma_f16(acc[g][nf][1], a1, b0, b1);
                }
            }
        }
        __syncthreads();
        if (c + 2 < 4) { issue_chunk(c + 2, buf); cp_commit(); }
    }

    // ---- epilogue: LSTM cell, all 4 gates thread-local (16 cells/thread) ----
    __half* HW = d_Hh + (size_t)(wb * 2 + dir) * NW * HID;
    const int jbase = j0 + wj * 16;
#pragma unroll
    for (int mh = 0; mh < 2; mh++) {
#pragma unroll
        for (int rh = 0; rh < 2; rh++) {
            int s = slot0 + ws * 32 + mh * 16 + rh * 8 + g4;
            if (s >= nact) continue;
            int v = d_chars[dir][t][s];
            bool last = (t == (int)d_slot_len[s] - 1);
            float* crow = &d_C[((size_t)dir * NW + s) * HID];
            float* frow = &d_Hfin[((size_t)dir * NW + s) * HID];
            __half* hrow = &HW[(size_t)s * HID];
            const __half* Pv = &d_P4[(((size_t)(dir * VOCAB + v) * HID) << 2)];
#pragma unroll
            for (int nf = 0; nf < 2; nf++) {
                int jp = jbase + nf * 8 + 2 * t4;
                uint4 pk = *reinterpret_cast<const uint4*>(&Pv[jp << 2]);
                const __half2* ph = reinterpret_cast<const __half2*>(&pk);
                float2 cc = *reinterpret_cast<const float2*>(&crow[jp]);
                float cin[2] = {cc.x, cc.y};
                float hv[2], cv[2];
#pragma unroll
                for (int cp = 0; cp < 2; cp++) {
                    float ai = acc[0][nf][mh][rh * 2 + cp] + __half2float(ph[2 * cp].x);
                    float af = acc[1][nf][mh][rh * 2 + cp] + __half2float(ph[2 * cp].y);
                    float ag = acc[2][nf][mh][rh * 2 + cp] + __half2float(ph[2 * cp + 1].x);
                    float ao = acc[3][nf][mh][rh * 2 + cp] + __half2float(ph[2 * cp + 1].y);
                    float c2 = sigm(af) * cin[cp] + sigm(ai) * ftanh(ag);
                    float h2 = sigm(ao) * ftanh(c2);
                    cv[cp] = c2;
                    hv[cp] = h2;
                }
                *reinterpret_cast<float2*>(&crow[jp]) = make_float2(cv[0], cv[1]);
                if (last)
                    *reinterpret_cast<float2*>(&frow[jp]) = make_float2(hv[0], hv[1]);
                __half2 h2v;
                h2v.x = __float2half_rn(hv[0]);
                h2v.y = __float2half_rn(hv[1]);
                *reinterpret_cast<__half2*>(&hrow[jp]) = h2v;
            }
        }
    }
    gdc_launch();
}

// ---------------- gather output ----------------
__global__ void k_out(float* __restrict__ out) {
    gdc_wait();
    int s = blockIdx.x;
    int tid = threadIdx.x;
    int w = d_word_of_slot[s];
    int dir = tid >> 8, j = tid & 255;
    out[(size_t)w * 512 + tid] = d_Hfin[((size_t)dir * NW + s) * HID + j];
}

// ---------------- launch ----------------
extern "C" void kernel_launch(void* const* d_in, const int* in_sizes, int n_in,
                              void* d_out, int out_size) {
    const int*   char_ids = (const int*)d_in[0];
    const int*   lengths  = (const int*)d_in[1];
    const float* emb      = (const float*)d_in[2];
    const float* WihF = (const float*)d_in[3];
    const float* WhhF = (const float*)d_in[4];
    const float* bihF = (const float*)d_in[5];
    const float* bhhF = (const float*)d_in[6];
    const float* WihB = (const float*)d_in[7];
    const float* WhhB = (const float*)d_in[8];
    const float* bihB = (const float*)d_in[9];
    const float* bhhB = (const float*)d_in[10];
    float* out = (float*)d_out;

    static bool s_init = false;
    if (!s_init) {
        cudaFuncSetAttribute(k_step, cudaFuncAttributeMaxDynamicSharedMemorySize, SM_TOT);
        s_init = true;
    }

    k_setup<<<1, 1024>>>(lengths);
    k_prep<<<2048 + 256, 256>>>(emb, WihF, bihF, bhhF, WihB, bihB, bhhB, WhhF, WhhB);
    k_scatter0<<<NW / 64, 512>>>(lengths, char_ids);

    cudaLaunchAttribute pdl[1];
    pdl[0].id = cudaLaunchAttributeProgrammaticStreamSerialization;
    pdl[0].val.programmaticStreamSerializationAllowed = 1;
    for (int t = 1; t < MAXLEN; t++) {
        cudaLaunchConfig_t cfg = {};
        cfg.gridDim = dim3(NW / 64, 4, 2);
        cfg.blockDim = dim3(256, 1, 1);
        cfg.dynamicSmemBytes = SM_TOT;
        cfg.stream = 0;
        cfg.attrs = pdl;
        cfg.numAttrs = 1;
        cudaLaunchKernelEx(&cfg, k_step, t);
    }
    {
        cudaLaunchConfig_t cfg = {};
        cfg.gridDim = dim3(NW, 1, 1);
        cfg.blockDim = dim3(512, 1, 1);
        cfg.dynamicSmemBytes = 0;
        cfg.stream = 0;
        cfg.attrs = pdl;
        cfg.numAttrs = 1;
        cudaLaunchKernelEx(&cfg, k_out, out);
    }
}

// round 17
// speedup vs baseline: 1.0591x; 1.0581x over previous
#include <cuda_runtime.h>
#include <cuda_fp16.h>
#include <cstdint>

#define NW     16384
#define MAXLEN 16
#define VOCAB  128
#define EMB    64
#define HID    256
#define G4     1024

// ---------------- static device state (no allocation) ----------------
// P table fp16, gate-interleaved: [dir][v][j 0..255][gate i,f,g,o]
__device__ __align__(16) __half d_P4[(size_t)2 * VOCAB * HID * 4];
__device__ float d_C[(size_t)2 * NW * HID];           // c: [dir][slot][j]
__device__ float d_Hfin[(size_t)2 * NW * HID];        // final h: [dir][slot][j]
// H fp16: [buf][dir][slot][k]
__device__ __align__(16) __half d_Hh[(size_t)2 * 2 * NW * HID];
// W u64-interleaved, chunked: [dir][jb(8)][chunk(4)][128 rows][pitch 20 u64]
__device__ __align__(16) __half d_Wimg[(size_t)2 * 8 * 4 * 128 * 80];
__device__ int   d_cursor[MAXLEN + 2];
__device__ int   d_offset[MAXLEN + 2];
__device__ int   d_nactive[MAXLEN];
__device__ int   d_word_of_slot[NW];
__device__ unsigned char d_slot_len[NW];
__device__ unsigned char d_chars[2][MAXLEN][NW];

// ---------------- helpers ----------------
__device__ __forceinline__ float sigm(float x) {
    return __fdividef(1.f, 1.f + __expf(-x));
}
__device__ __forceinline__ float ftanh(float x) {
    float e = __expf(-2.f * x);
    return __fdividef(1.f - e, 1.f + e);
}
__device__ __forceinline__ void mma_f16(float c[4], const uint32_t a[4],
                                        uint32_t b0, uint32_t b1) {
    asm volatile(
        "mma.sync.aligned.m16n8k16.row.col.f32.f16.f16.f32 "
        "{%0,%1,%2,%3}, {%4,%5,%6,%7}, {%8,%9}, {%0,%1,%2,%3};"
        : "+f"(c[0]), "+f"(c[1]), "+f"(c[2]), "+f"(c[3])
        : "r"(a[0]), "r"(a[1]), "r"(a[2]), "r"(a[3]), "r"(b0), "r"(b1));
}
__device__ __forceinline__ void ldsm4(uint32_t r[4], uint32_t addr) {
    asm volatile("ldmatrix.sync.aligned.m8n8.x4.shared.b16 {%0,%1,%2,%3}, [%4];"
        : "=r"(r[0]), "=r"(r[1]), "=r"(r[2]), "=r"(r[3]) : "r"(addr));
}
__device__ __forceinline__ void lds64(uint32_t& b0, uint32_t& b1, uint32_t addr) {
    asm volatile("ld.shared.v2.b32 {%0,%1}, [%2];" : "=r"(b0), "=r"(b1) : "r"(addr));
}
__device__ __forceinline__ uint32_t smem_u32(const void* p) {
    uint32_t a;
    asm("{ .reg .u64 t; cvta.to.shared.u64 t, %1; cvt.u32.u64 %0, t; }" : "=r"(a) : "l"(p));
    return a;
}
__device__ __forceinline__ void cp16(uint32_t dst, const void* src) {
    asm volatile("cp.async.cg.shared.global [%0], [%1], 16;" :: "r"(dst), "l"(src) : "memory");
}
__device__ __forceinline__ void cp_commit() {
    asm volatile("cp.async.commit_group;" ::: "memory");
}
template <int N>
__device__ __forceinline__ void cp_wait() {
    asm volatile("cp.async.wait_group %0;" :: "n"(N) : "memory");
}
__device__ __forceinline__ void gdc_wait() {
    asm volatile("griddepcontrol.wait;" ::: "memory");
}
__device__ __forceinline__ void gdc_launch() {
    asm volatile("griddepcontrol.launch_dependents;" ::: "memory");
}

// ---------------- setup: hist + scan + cursor (one block) ----------------
__global__ void k_setup(const int* __restrict__ lengths) {
    __shared__ int sh[MAXLEN + 2];
    int tid = threadIdx.x;                      // 1024
    if (tid <= MAXLEN + 1) sh[tid] = 0;
    __syncthreads();
    for (int w = tid; w < NW; w += 1024) atomicAdd(&sh[lengths[w]], 1);
    __syncthreads();
    if (tid == 0) {
        int off = 0;
        for (int L = MAXLEN; L >= 1; L--) { d_offset[L] = off; off += sh[L]; }
        for (int t = 0; t < MAXLEN; t++) {
            int n = 0;
            for (int L = t + 1; L <= MAXLEN; L++) n += sh[L];
            d_nactive[t] = n;
        }
    }
    if (tid <= MAXLEN + 1) d_cursor[tid] = 0;
}

// ---------------- prep: W u64-interleaved chunked image + P4 table ----------------
__global__ void k_prep(const float* __restrict__ emb,
                       const float* __restrict__ WihF, const float* __restrict__ bihF,
                       const float* __restrict__ bhhF,
                       const float* __restrict__ WihB, const float* __restrict__ bihB,
                       const float* __restrict__ bhhB,
                       const float* __restrict__ WhhF, const float* __restrict__ WhhB) {
    if (blockIdx.x < 2048) {
        int i = blockIdx.x * 256 + threadIdx.x;    // 2*1024*256
        int dir = i >> 18;
        int e = i & 0x3FFFF;
        int row = e >> 8, k = e & 255;
        int g = row >> 8, j = row & 255;
        int jb = j >> 5, jl = j & 31;
        int r128 = g * 32 + jl;
        int ch = k >> 6, kl = k & 63;
        int q = (kl >> 4) * 4 + ((kl & 7) >> 1);
        int pos = (kl & 1) + (((kl & 15) >= 8) ? 2 : 0);
        float x = (dir ? WhhB : WhhF)[(size_t)row * 256 + k];
        d_Wimg[(((size_t)((dir * 8 + jb) * 4 + ch) * 128 + r128) * 20 + q) * 4 + pos]
            = __float2half_rn(x);
    } else {
        int bid = blockIdx.x - 2048;
        int v = bid & 127, d = bid >> 7;
        const float* Wih = d ? WihB : WihF;
        const float* bih = d ? bihB : bihF;
        const float* bhh = d ? bhhB : bhhF;
        __shared__ float esm[EMB];
        if (threadIdx.x < EMB) esm[threadIdx.x] = emb[v * EMB + threadIdx.x];
        __syncthreads();
#pragma unroll
        for (int q = 0; q < 4; q++) {
            int j = threadIdx.x + q * 256;         // 0..1023 gate-major row
            const float* wr = &Wih[j * EMB];
            float s = 0.f;
#pragma unroll
            for (int k = 0; k < EMB; k += 4) {
                float4 wv = *reinterpret_cast<const float4*>(&wr[k]);
                s += esm[k] * wv.x + esm[k + 1] * wv.y + esm[k + 2] * wv.z + esm[k + 3] * wv.w;
            }
            int g = j >> 8, jc = j & 255;
            d_P4[(((size_t)(d * VOCAB + v) * HID + jc) << 2) + g]
                = __float2half_rn(s + bih[j] + bhh[j]);
        }
    }
}

// ---------------- scatter + step 0 (h0 = 0 -> gates = P[char]) ----------------
__global__ void __launch_bounds__(512)
k_scatter0(const int* __restrict__ lengths, const int* __restrict__ char_ids) {
    int tid = threadIdx.x;
    int wloc = tid >> 3, sub = tid & 7;
    int w = blockIdx.x * 64 + wloc;
    __shared__ int spos[64];
    int len = lengths[w];
    if (sub == 0) {
        int pos = d_offset[len] + atomicAdd(&d_cursor[len], 1);
        spos[wloc] = pos;
        d_word_of_slot[pos] = w;
        d_slot_len[pos] = (unsigned char)len;
    }
    __syncthreads();
    int pos = spos[wloc];
#pragma unroll
    for (int tt = sub * 2; tt < sub * 2 + 2; tt++) {
        d_chars[0][tt][pos] = (unsigned char)char_ids[w * MAXLEN + tt];
        int r = len - 1 - tt; if (r < 0) r = 0;
        d_chars[1][tt][pos] = (unsigned char)char_ids[w * MAXLEN + r];
    }
    int dir = sub >> 2;
    int j0 = (sub & 3) * 64;
    int v = char_ids[w * MAXLEN + (dir ? (len - 1) : 0)];
    const __half* Pv = d_P4 + (((size_t)(dir * VOCAB + v) * HID) << 2);
    bool last = (len == 1);
    float* crow = &d_C[((size_t)dir * NW + pos) * HID];
    float* frow = &d_Hfin[((size_t)dir * NW + pos) * HID];
    __half* hrow = d_Hh + ((size_t)(2 + dir) * NW + pos) * HID;   // buf 1
#pragma unroll 2
    for (int q = 0; q < 64; q += 2) {
        float hv[2];
        uint4 pk = *reinterpret_cast<const uint4*>(&Pv[(j0 + q) << 2]);
        const __half2* ph = reinterpret_cast<const __half2*>(&pk);
#pragma unroll
        for (int u = 0; u < 2; u++) {
            int j = j0 + q + u;
            float pi = __half2float(ph[2 * u].x);
            float pg = __half2float(ph[2 * u + 1].x);
            float po = __half2float(ph[2 * u + 1].y);
            float c1 = sigm(pi) * ftanh(pg);
            float h1 = sigm(po) * ftanh(c1);
            crow[j] = c1;
            if (last) frow[j] = h1;
            hv[u] = h1;
        }
        __half2 h2v; h2v.x = __float2half_rn(hv[0]); h2v.y = __float2half_rn(hv[1]);
        *reinterpret_cast<__half2*>(&hrow[j0 + q]) = h2v;
    }
}

// ---------------- fused recurrent step (t >= 1) ----------------
// Block: 64 slots x 32 j x 4 gates, 8 warps. Warp tile 32 slots x 32 n (square).
// W staged BEFORE gdc_wait (independent of predecessor); A staged after.
#define TILE_A  9216                           // 64 * 144
#define TILE_W  20480                          // 128 * 160
#define SM_W0   (2 * TILE_A)                   // 18432
#define SM_TOT  (SM_W0 + 2 * TILE_W)           // 59392

__global__ void __launch_bounds__(256, 3) k_step(int t) {
    const int jb = blockIdx.y, j0 = jb * 32;
    const int dir = blockIdx.z;
    const int rb = t & 1, wb = rb ^ 1;
    const int slot0 = blockIdx.x * 64;

    extern __shared__ __align__(16) char smem[];
    const uint32_t sb = smem_u32(smem);
    const char* wimg = (const char*)d_Wimg + (size_t)(dir * 8 + jb) * 4 * TILE_W;

    const int tid = threadIdx.x;
    const int warp = tid >> 5, lane = tid & 31;
    const int ws = warp & 1, wj = warp >> 1;
    const int g4 = lane >> 2, t4 = lane & 3;

    // ---- W staging for chunks 0,1 (predecessor-independent) ----
    auto issue_W = [&](int c, int buf) {
        uint32_t wsB = sb + SM_W0 + buf * TILE_W;
        const char* wsrc = wimg + c * TILE_W;
#pragma unroll
        for (int i = 0; i < 5; i++) {
            int r = (tid + i * 256) * 16;
            cp16(wsB + r, wsrc + r);
        }
    };
    issue_W(0, 0);
    issue_W(1, 1);
    cp_commit();                               // group: W01

    gdc_wait();                                // PDL: prior step's H fully visible

    const int nact = d_nactive[t];
    if (slot0 >= nact) { gdc_launch(); cp_wait<0>(); return; }

    // ---- epilogue-scalar prefetch (scattered u8 loads, hidden under GEMM) ----
    int vv[2][2]; bool lastf[2][2]; bool live[2][2];
#pragma unroll
    for (int mh = 0; mh < 2; mh++)
#pragma unroll
        for (int rh = 0; rh < 2; rh++) {
            int s = slot0 + ws * 32 + mh * 16 + rh * 8 + g4;
            live[mh][rh] = (s < nact);
            int sc = live[mh][rh] ? s : 0;
            vv[mh][rh] = d_chars[dir][t][sc];
            lastf[mh][rh] = (t == (int)d_slot_len[sc] - 1);
        }

    const char* __restrict__ Hr = (const char*)(d_Hh + (size_t)(rb * 2 + dir) * NW * HID);
    const int sA0 = tid >> 3, koA = (tid & 7) * 16;
    auto issue_A = [&](int c, int buf) {
        uint32_t asB = sb + buf * TILE_A;
        cp16(asB + sA0 * 144 + koA,
             Hr + (size_t)(slot0 + sA0) * 512 + c * 128 + koA);
        cp16(asB + (sA0 + 32) * 144 + koA,
             Hr + (size_t)(slot0 + sA0 + 32) * 512 + c * 128 + koA);
    };
    issue_A(0, 0); cp_commit();                // group: A0
    issue_A(1, 1); cp_commit();                // group: A1

    const uint32_t arow_off = (uint32_t)(ws * 32 + (lane & 15)) * 144 + ((lane & 16) ? 16 : 0);

    float acc[4][2][4];                        // [gate][mh][frag]
#pragma unroll
    for (int g = 0; g < 4; g++)
#pragma unroll
        for (int mh = 0; mh < 2; mh++)
#pragma unroll
            for (int r = 0; r < 4; r++) acc[g][mh][r] = 0.f;

#pragma unroll 1
    for (int c = 0; c < 4; c++) {
        if (c < 3) cp_wait<1>(); else cp_wait<0>();
        __syncthreads();
        const int buf = c & 1;
        const uint32_t aB = sb + buf * TILE_A + arow_off;
        const uint32_t wB = sb + SM_W0 + buf * TILE_W;
#pragma unroll
        for (int kk4 = 0; kk4 < 4; kk4++) {
            uint32_t a0[4], a1[4];
            ldsm4(a0, aB + kk4 * 32);
            ldsm4(a1, aB + 2304 + kk4 * 32);      // mh=1: +16 rows * 144 B
            const int qb = kk4 * 4 + t4;
#pragma unroll
            for (int g = 0; g < 4; g++) {
                int row = g * 32 + wj * 8 + g4;
                uint32_t b0, b1;
                lds64(b0, b1, wB + (uint32_t)(row * 20 + qb) * 8);
                mma_f16(acc[g][0], a0, b0, b1);
                mma_f16(acc[g][1], a1, b0, b1);
            }
        }
        __syncthreads();
        if (c + 2 < 4) { issue_A(c + 2, buf); issue_W(c + 2, buf); cp_commit(); }
    }

    // ---- epilogue: LSTM cell, all 4 gates thread-local (8 cells/thread) ----
    __half* HW = d_Hh + (size_t)(wb * 2 + dir) * NW * HID;
    const int jp = j0 + wj * 8 + 2 * t4;
#pragma unroll
    for (int mh = 0; mh < 2; mh++) {
#pragma unroll
        for (int rh = 0; rh < 2; rh++) {
            if (!live[mh][rh]) continue;
            int s = slot0 + ws * 32 + mh * 16 + rh * 8 + g4;
            int v = vv[mh][rh];
            bool last = lastf[mh][rh];
            float* crow = &d_C[((size_t)dir * NW + s) * HID];
            float* frow = &d_Hfin[((size_t)dir * NW + s) * HID];
            __half* hrow = &HW[(size_t)s * HID];
            uint4 pk = *reinterpret_cast<const uint4*>(
                &d_P4[((((size_t)(dir * VOCAB + v) * HID) + jp) << 2)]);
            const __half2* ph = reinterpret_cast<const __half2*>(&pk);
            float2 cc = *reinterpret_cast<const float2*>(&crow[jp]);
            float cin[2] = {cc.x, cc.y};
            float hv[2], cv[2];
#pragma unroll
            for (int cp = 0; cp < 2; cp++) {
                float ai = acc[0][mh][rh * 2 + cp] + __half2float(ph[2 * cp].x);
                float af = acc[1][mh][rh * 2 + cp] + __half2float(ph[2 * cp].y);
                float ag = acc[2][mh][rh * 2 + cp] + __half2float(ph[2 * cp + 1].x);
                float ao = acc[3][mh][rh * 2 + cp] + __half2float(ph[2 * cp + 1].y);
                float c2 = sigm(af) * cin[cp] + sigm(ai) * ftanh(ag);
                float h2 = sigm(ao) * ftanh(c2);
                cv[cp] = c2;
                hv[cp] = h2;
            }
            *reinterpret_cast<float2*>(&crow[jp]) = make_float2(cv[0], cv[1]);
            if (last)
                *reinterpret_cast<float2*>(&frow[jp]) = make_float2(hv[0], hv[1]);
            __half2 h2v;
            h2v.x = __float2half_rn(hv[0]);
            h2v.y = __float2half_rn(hv[1]);
            *reinterpret_cast<__half2*>(&hrow[jp]) = h2v;
        }
    }
    gdc_launch();
}

// ---------------- gather output ----------------
__global__ void k_out(float* __restrict__ out) {
    gdc_wait();
    int s = blockIdx.x;
    int tid = threadIdx.x;
    int w = d_word_of_slot[s];
    int dir = tid >> 8, j = tid & 255;
    out[(size_t)w * 512 + tid] = d_Hfin[((size_t)dir * NW + s) * HID + j];
}

// ---------------- launch ----------------
extern "C" void kernel_launch(void* const* d_in, const int* in_sizes, int n_in,
                              void* d_out, int out_size) {
    const int*   char_ids = (const int*)d_in[0];
    const int*   lengths  = (const int*)d_in[1];
    const float* emb      = (const float*)d_in[2];
    const float* WihF = (const float*)d_in[3];
    const float* WhhF = (const float*)d_in[4];
    const float* bihF = (const float*)d_in[5];
    const float* bhhF = (const float*)d_in[6];
    const float* WihB = (const float*)d_in[7];
    const float* WhhB = (const float*)d_in[8];
    const float* bihB = (const float*)d_in[9];
    const float* bhhB = (const float*)d_in[10];
    float* out = (float*)d_out;

    static bool s_init = false;
    if (!s_init) {
        cudaFuncSetAttribute(k_step, cudaFuncAttributeMaxDynamicSharedMemorySize, SM_TOT);
        s_init = true;
    }

    k_setup<<<1, 1024>>>(lengths);
    k_prep<<<2048 + 256, 256>>>(emb, WihF, bihF, bhhF, WihB, bihB, bhhB, WhhF, WhhB);
    k_scatter0<<<NW / 64, 512>>>(lengths, char_ids);

    cudaLaunchAttribute pdl[1];
    pdl[0].id = cudaLaunchAttributeProgrammaticStreamSerialization;
    pdl[0].val.programmaticStreamSerializationAllowed = 1;
    for (int t = 1; t < MAXLEN; t++) {
        cudaLaunchConfig_t cfg = {};
        cfg.gridDim = dim3(NW / 64, 8, 2);
        cfg.blockDim = dim3(256, 1, 1);
        cfg.dynamicSmemBytes = SM_TOT;
        cfg.stream = 0;
        cfg.attrs = pdl;
        cfg.numAttrs = 1;
        cudaLaunchKernelEx(&cfg, k_step, t);
    }
    {
        cudaLaunchConfig_t cfg = {};
        cfg.gridDim = dim3(NW, 1, 1);
        cfg.blockDim = dim3(512, 1, 1);
        cfg.dynamicSmemBytes = 0;
        cfg.stream = 0;
        cfg.attrs = pdl;
        cfg.numAttrs = 1;
        cudaLaunchKernelEx(&cfg, k_out, out);
    }
}